// round 1
// baseline (speedup 1.0000x reference)
#include <cuda_runtime.h>
#include <math.h>

#define BB 8
#define SS 785
#define DD 128
#define HH 8
#define DHD 64
#define DFF 512
#define LL 6
#define HWP 784
#define CINC 512
#define BSR (BB*SS)   // 6280

// ------------------------- scratch (device globals) -------------------------
__device__ float g_xs[BSR*DD];
__device__ float g_xf[BSR*DD];
__device__ float g_q[BSR*512];
__device__ float g_k[BSR*512];
__device__ float g_v[BSR*512];
__device__ float g_s512[BSR*512];
__device__ float g_s128[BSR*DD];
__device__ float g_wt[CINC*DD];
__device__ float g_tb[DD];
__device__ unsigned g_maxbits;

// ------------------------- prep: fold BN into conv W ------------------------
__global__ void prep_kernel(const float* __restrict__ conv_w,
                            const float* __restrict__ gamma,
                            const float* __restrict__ beta,
                            const float* __restrict__ mean,
                            const float* __restrict__ var) {
    int i = blockIdx.x * blockDim.x + threadIdx.x;
    if (i == 0) g_maxbits = 0u;
    if (i < DD) {
        float s = gamma[i] * rsqrtf(var[i] + 1e-5f);
        g_tb[i] = beta[i] - mean[i] * s;
    }
    if (i < CINC * DD) {
        int c = i / DD, d = i % DD;
        float s = gamma[d] * rsqrtf(var[d] + 1e-5f);
        g_wt[i] = conv_w[d * CINC + c] * s;
    }
}

// ------------------ conv stem: 1x1 conv + BN + relu + max -------------------
// out[b, 1+p, d] written raw (pre-normalization) into g_xs / g_xf
__global__ __launch_bounds__(256) void conv_kernel(const float* __restrict__ x,
                                                   const float* __restrict__ y) {
    const int pb = blockIdx.x * 64;
    const int b  = blockIdx.y;
    const int st = blockIdx.z;
    const float* src = (st == 0) ? x : y;
    float* dst = (st == 0) ? g_xs : g_xf;

    __shared__ float Xs[16 * 64];   // [c][p]
    __shared__ float Ws[16 * 128];  // [c][d]

    const int t  = threadIdx.x;
    const int tx = t & 15;          // d-group (8 d's)
    const int ty = t >> 4;          // p-group (4 p's)

    float acc[4][8];
    #pragma unroll
    for (int i = 0; i < 4; i++)
        #pragma unroll
        for (int j = 0; j < 8; j++) acc[i][j] = 0.f;

    for (int c0 = 0; c0 < CINC; c0 += 16) {
        // load X tile: thread -> (cc = t/16, pp = (t%16)*4)
        {
            int cc = t >> 4, pp = (t & 15) << 2;
            int p = pb + pp;
            float4 v = make_float4(0.f, 0.f, 0.f, 0.f);
            if (p < HWP)
                v = *(const float4*)&src[((size_t)(b * CINC) + (c0 + cc)) * HWP + p];
            *(float4*)&Xs[cc * 64 + pp] = v;
        }
        // load W tile: thread -> (cc = t/16, dd = (t%16)*8)
        {
            int cc = t >> 4, ddv = (t & 15) << 3;
            const float* wp = &g_wt[(c0 + cc) * DD + ddv];
            *(float4*)&Ws[cc * 128 + ddv]     = *(const float4*)(wp);
            *(float4*)&Ws[cc * 128 + ddv + 4] = *(const float4*)(wp + 4);
        }
        __syncthreads();
        #pragma unroll
        for (int kk = 0; kk < 16; kk++) {
            float4 a  = *(float4*)&Xs[kk * 64 + (ty << 2)];
            float4 w0 = *(float4*)&Ws[kk * 128 + (tx << 3)];
            float4 w1 = *(float4*)&Ws[kk * 128 + (tx << 3) + 4];
            float av[4] = {a.x, a.y, a.z, a.w};
            float wv[8] = {w0.x, w0.y, w0.z, w0.w, w1.x, w1.y, w1.z, w1.w};
            #pragma unroll
            for (int i = 0; i < 4; i++)
                #pragma unroll
                for (int j = 0; j < 8; j++) acc[i][j] = fmaf(av[i], wv[j], acc[i][j]);
        }
        __syncthreads();
    }

    float lmax = 0.f;
    #pragma unroll
    for (int i = 0; i < 4; i++) {
        int p = pb + (ty << 2) + i;
        if (p < HWP) {
            #pragma unroll
            for (int j = 0; j < 8; j++) {
                int d = (tx << 3) + j;
                float v = fmaxf(acc[i][j] + g_tb[d], 0.f);
                lmax = fmaxf(lmax, v);
                dst[((size_t)(b * SS) + 1 + p) * DD + d] = v;
            }
        }
    }
    __shared__ float red[256];
    red[t] = lmax;
    __syncthreads();
    for (int stx = 128; stx > 0; stx >>= 1) {
        if (t < stx) red[t] = fmaxf(red[t], red[t + stx]);
        __syncthreads();
    }
    if (t == 0) atomicMax(&g_maxbits, __float_as_uint(red[0]));
}

// --------------- assemble: cls row, /max, +pos for both streams -------------
__global__ void assemble_kernel(const float* __restrict__ pos,
                                const float* __restrict__ cls) {
    int i = blockIdx.x * blockDim.x + threadIdx.x;
    if (i >= BSR * DD) return;
    float inv = 1.f / __uint_as_float(g_maxbits);
    int d = i & (DD - 1);
    int s = (i / DD) % SS;
    float p = pos[s * DD + d];
    if (s == 0) {
        float v = cls[d] + p;
        g_xs[i] = v;
        g_xf[i] = v;
    } else {
        g_xs[i] = g_xs[i] * inv + p;
        g_xf[i] = g_xf[i] * inv + p;
    }
}

// ------------------------- generic SGEMM, bias + act ------------------------
// C[M,N] = act(A[M,K] @ B[K,N] + bias[N]);  N % 64 == 0, K % 16 == 0
template <int ACT>
__global__ __launch_bounds__(256) void gemm_kernel(const float* __restrict__ A,
                                                   const float* __restrict__ Bm,
                                                   const float* __restrict__ bias,
                                                   float* __restrict__ C,
                                                   int M, int N, int K) {
    __shared__ float As[16 * 64];  // [k][m]
    __shared__ float Bs[16 * 64];  // [k][n]
    const int t  = threadIdx.x;
    const int tx = t & 15, ty = t >> 4;
    const int m0 = blockIdx.y * 64, n0 = blockIdx.x * 64;

    float acc[4][4];
    #pragma unroll
    for (int i = 0; i < 4; i++)
        #pragma unroll
        for (int j = 0; j < 4; j++) acc[i][j] = 0.f;

    for (int k0 = 0; k0 < K; k0 += 16) {
        {
            int row = t >> 2, kk = (t & 3) << 2;
            float4 av = make_float4(0.f, 0.f, 0.f, 0.f);
            if (m0 + row < M)
                av = *(const float4*)&A[(size_t)(m0 + row) * K + k0 + kk];
            As[(kk + 0) * 64 + row] = av.x;
            As[(kk + 1) * 64 + row] = av.y;
            As[(kk + 2) * 64 + row] = av.z;
            As[(kk + 3) * 64 + row] = av.w;
        }
        {
            int kr = t >> 4, nc = (t & 15) << 2;
            *(float4*)&Bs[kr * 64 + nc] =
                *(const float4*)&Bm[(size_t)(k0 + kr) * N + n0 + nc];
        }
        __syncthreads();
        #pragma unroll
        for (int kk = 0; kk < 16; kk++) {
            float4 a = *(float4*)&As[kk * 64 + (ty << 2)];
            float4 b = *(float4*)&Bs[kk * 64 + (tx << 2)];
            float av[4] = {a.x, a.y, a.z, a.w};
            float bv[4] = {b.x, b.y, b.z, b.w};
            #pragma unroll
            for (int i = 0; i < 4; i++)
                #pragma unroll
                for (int j = 0; j < 4; j++) acc[i][j] = fmaf(av[i], bv[j], acc[i][j]);
        }
        __syncthreads();
    }

    #pragma unroll
    for (int i = 0; i < 4; i++) {
        int r = m0 + (ty << 2) + i;
        if (r < M) {
            #pragma unroll
            for (int j = 0; j < 4; j++) {
                int c = n0 + (tx << 2) + j;
                float v = acc[i][j] + bias[c];
                if (ACT == 1) v = v * normcdff(v);  // exact GELU
                C[(size_t)r * N + c] = v;
            }
        }
    }
}

// ------------------------- fused flash attention ----------------------------
// grid (13, H, B), 256 threads. reads g_q/g_k/g_v ([b,s,h*64+d]), writes g_s512
__global__ __launch_bounds__(256) void attn_kernel(const int* __restrict__ enc) {
    extern __shared__ float smem[];
    float* Qs = smem;               // [d][i]  64x64
    float* Ks = smem + 4096;        // [d][j]  64x64
    float* Vs = smem + 8192;        // [k][d]  64x64
    float* Ps = smem + 12288;       // [i][k]  64x68

    const int qt = blockIdx.x, h = blockIdx.y, b = blockIdx.z;
    const int q0 = qt * 64;
    const int t  = threadIdx.x;
    const int tx = t & 15, ty = t >> 4;

    // load Q tile (transposed into [d][i])
    {
        int i = t >> 2, dv = (t & 3) << 4;
        int s = q0 + i;
        bool ok = s < SS;
        const float* qp = &g_q[(size_t)(b * SS + (ok ? s : 0)) * 512 + h * 64 + dv];
        #pragma unroll
        for (int u = 0; u < 16; u += 4) {
            float4 v = ok ? *(const float4*)(qp + u) : make_float4(0, 0, 0, 0);
            Qs[(dv + u + 0) * 64 + i] = v.x;
            Qs[(dv + u + 1) * 64 + i] = v.y;
            Qs[(dv + u + 2) * 64 + i] = v.z;
            Qs[(dv + u + 3) * 64 + i] = v.w;
        }
    }

    float m[4], l[4], o[4][4];
    #pragma unroll
    for (int i = 0; i < 4; i++) {
        m[i] = -1e30f;
        l[i] = 0.f;
        #pragma unroll
        for (int j = 0; j < 4; j++) o[i][j] = 0.f;
    }
    const float scale = 0.125f;  // 1/sqrt(64)

    for (int t0 = 0; t0 < SS; t0 += 64) {
        __syncthreads();
        // load K (transposed) and V tiles
        {
            int j = t >> 2, dv = (t & 3) << 4;
            int s = t0 + j;
            bool ok = s < SS;
            const float* kp = &g_k[(size_t)(b * SS + (ok ? s : 0)) * 512 + h * 64 + dv];
            const float* vp = &g_v[(size_t)(b * SS + (ok ? s : 0)) * 512 + h * 64 + dv];
            #pragma unroll
            for (int u = 0; u < 16; u += 4) {
                float4 kv = ok ? *(const float4*)(kp + u) : make_float4(0, 0, 0, 0);
                Ks[(dv + u + 0) * 64 + j] = kv.x;
                Ks[(dv + u + 1) * 64 + j] = kv.y;
                Ks[(dv + u + 2) * 64 + j] = kv.z;
                Ks[(dv + u + 3) * 64 + j] = kv.w;
                float4 vv = ok ? *(const float4*)(vp + u) : make_float4(0, 0, 0, 0);
                *(float4*)&Vs[j * 64 + dv + u] = vv;
            }
        }
        __syncthreads();

        // scores S = Q K^T (each thread 4x4)
        float sc[4][4];
        #pragma unroll
        for (int i = 0; i < 4; i++)
            #pragma unroll
            for (int j = 0; j < 4; j++) sc[i][j] = 0.f;
        #pragma unroll 8
        for (int d = 0; d < 64; d++) {
            float4 q4 = *(float4*)&Qs[d * 64 + (ty << 2)];
            float4 k4 = *(float4*)&Ks[d * 64 + (tx << 2)];
            float qv[4] = {q4.x, q4.y, q4.z, q4.w};
            float kv[4] = {k4.x, k4.y, k4.z, k4.w};
            #pragma unroll
            for (int i = 0; i < 4; i++)
                #pragma unroll
                for (int j = 0; j < 4; j++) sc[i][j] = fmaf(qv[i], kv[j], sc[i][j]);
        }
        // scale + mask
        #pragma unroll
        for (int j = 0; j < 4; j++) {
            int kj = t0 + (tx << 2) + j;
            bool valid = (kj < SS) && (enc[b * SS + kj] != 0);
            #pragma unroll
            for (int i = 0; i < 4; i++)
                sc[i][j] = valid ? sc[i][j] * scale : -1e9f;
        }
        // online softmax row stats (reduce across the 16 tx lanes)
        #pragma unroll
        for (int i = 0; i < 4; i++) {
            float mx = fmaxf(fmaxf(sc[i][0], sc[i][1]), fmaxf(sc[i][2], sc[i][3]));
            #pragma unroll
            for (int off = 8; off > 0; off >>= 1)
                mx = fmaxf(mx, __shfl_xor_sync(0xffffffffu, mx, off));
            float mn = fmaxf(m[i], mx);
            float f  = __expf(m[i] - mn);
            float rs = 0.f;
            #pragma unroll
            for (int j = 0; j < 4; j++) {
                float p = __expf(sc[i][j] - mn);
                sc[i][j] = p;
                rs += p;
            }
            #pragma unroll
            for (int off = 8; off > 0; off >>= 1)
                rs += __shfl_xor_sync(0xffffffffu, rs, off);
            l[i] = l[i] * f + rs;
            m[i] = mn;
            #pragma unroll
            for (int j = 0; j < 4; j++) o[i][j] *= f;
        }
        // stage P
        #pragma unroll
        for (int i = 0; i < 4; i++)
            *(float4*)&Ps[((ty << 2) + i) * 68 + (tx << 2)] =
                make_float4(sc[i][0], sc[i][1], sc[i][2], sc[i][3]);
        __syncthreads();
        // O += P V (each thread 4 rows x 4 dims)
        #pragma unroll 8
        for (int k = 0; k < 64; k++) {
            float4 v4 = *(float4*)&Vs[k * 64 + (tx << 2)];
            #pragma unroll
            for (int i = 0; i < 4; i++) {
                float p = Ps[((ty << 2) + i) * 68 + k];
                o[i][0] = fmaf(p, v4.x, o[i][0]);
                o[i][1] = fmaf(p, v4.y, o[i][1]);
                o[i][2] = fmaf(p, v4.z, o[i][2]);
                o[i][3] = fmaf(p, v4.w, o[i][3]);
            }
        }
    }

    #pragma unroll
    for (int i = 0; i < 4; i++) {
        int s = q0 + (ty << 2) + i;
        if (s < SS) {
            float invl = 1.f / l[i];
            *(float4*)&g_s512[(size_t)(b * SS + s) * 512 + h * 64 + (tx << 2)] =
                make_float4(o[i][0] * invl, o[i][1] * invl, o[i][2] * invl, o[i][3] * invl);
        }
    }
}

// ---------------- residual add + LayerNorm (in-place on g_xs) ---------------
__global__ void ln_kernel(float* __restrict__ xs, const float* __restrict__ add,
                          const float* __restrict__ g, const float* __restrict__ bb) {
    int r = blockIdx.x;
    int d = threadIdx.x;
    float v = xs[(size_t)r * DD + d] + add[(size_t)r * DD + d];
    __shared__ float sred[4];
    float sv = v;
    #pragma unroll
    for (int off = 16; off > 0; off >>= 1) sv += __shfl_xor_sync(~0u, sv, off);
    if ((d & 31) == 0) sred[d >> 5] = sv;
    __syncthreads();
    float mu = (sred[0] + sred[1] + sred[2] + sred[3]) * (1.f / 128.f);
    float c = v - mu;
    float sq = c * c;
    #pragma unroll
    for (int off = 16; off > 0; off >>= 1) sq += __shfl_xor_sync(~0u, sq, off);
    __syncthreads();
    if ((d & 31) == 0) sred[d >> 5] = sq;
    __syncthreads();
    float var = (sred[0] + sred[1] + sred[2] + sred[3]) * (1.f / 128.f);
    xs[(size_t)r * DD + d] = c * rsqrtf(var + 1e-12f) * g[d] + bb[d];
}

// --------------------------------- head -------------------------------------
__global__ void head_kernel(const float* __restrict__ w1,
                            const float* __restrict__ w2,
                            float* __restrict__ out) {
    int b = blockIdx.x, j = threadIdx.x;
    const float* xr = &g_xs[(size_t)(b * SS) * DD];
    float s = 0.f;
    #pragma unroll
    for (int d = 0; d < DD; d++) s = fmaf(xr[d], w1[d * 512 + j], s);
    s = fmaxf(s, 0.f) * w2[j];
    __shared__ float red[512];
    red[j] = s;
    __syncthreads();
    for (int st = 256; st > 0; st >>= 1) {
        if (j < st) red[j] += red[j + st];
        __syncthreads();
    }
    if (j == 0) out[b] = red[0];
}

// ------------------------------ launcher ------------------------------------
extern "C" void kernel_launch(void* const* d_in, const int* in_sizes, int n_in,
                              void* d_out, int out_size) {
    const float* conv_w   = (const float*)d_in[0];
    const float* bn_gamma = (const float*)d_in[1];
    const float* bn_beta  = (const float*)d_in[2];
    const float* bn_mean  = (const float*)d_in[3];
    const float* bn_var   = (const float*)d_in[4];
    const float* pos_emb  = (const float*)d_in[5];
    const float* cls_tok  = (const float*)d_in[6];
    const float* Wq = (const float*)d_in[7];
    const float* bq = (const float*)d_in[8];
    const float* Wk = (const float*)d_in[9];
    const float* bk = (const float*)d_in[10];
    const float* Wv = (const float*)d_in[11];
    const float* bv = (const float*)d_in[12];
    const float* Wo = (const float*)d_in[13];
    const float* bo = (const float*)d_in[14];
    const float* ln1_g = (const float*)d_in[15];
    const float* ln1_b = (const float*)d_in[16];
    const float* fw1 = (const float*)d_in[17];
    const float* fb1 = (const float*)d_in[18];
    const float* fw2 = (const float*)d_in[19];
    const float* fb2 = (const float*)d_in[20];
    const float* ln2_g = (const float*)d_in[21];
    const float* ln2_b = (const float*)d_in[22];
    const float* pw1 = (const float*)d_in[23];
    const float* pw2 = (const float*)d_in[24];
    const int*   enc = (const int*)d_in[25];
    const float* x   = (const float*)d_in[26];
    const float* y   = (const float*)d_in[27];
    float* out = (float*)d_out;

    float *xs, *xf, *q, *k, *v, *s512, *s128;
    cudaGetSymbolAddress((void**)&xs,   g_xs);
    cudaGetSymbolAddress((void**)&xf,   g_xf);
    cudaGetSymbolAddress((void**)&q,    g_q);
    cudaGetSymbolAddress((void**)&k,    g_k);
    cudaGetSymbolAddress((void**)&v,    g_v);
    cudaGetSymbolAddress((void**)&s512, g_s512);
    cudaGetSymbolAddress((void**)&s128, g_s128);

    const int ATTN_SMEM = (64 * 64 * 3 + 64 * 68) * (int)sizeof(float);
    cudaFuncSetAttribute(attn_kernel, cudaFuncAttributeMaxDynamicSharedMemorySize,
                         ATTN_SMEM);

    prep_kernel<<<(CINC * DD + 255) / 256, 256>>>(conv_w, bn_gamma, bn_beta,
                                                  bn_mean, bn_var);
    conv_kernel<<<dim3(13, BB, 2), 256>>>(x, y);
    assemble_kernel<<<(BSR * DD + 255) / 256, 256>>>(pos_emb, cls_tok);

    const dim3 g512(8, (BSR + 63) / 64);
    const dim3 g128(2, (BSR + 63) / 64);

    for (int i = 0; i < LL; i++) {
        const float* Wqi = Wq + (size_t)i * DD * 512;
        const float* Wki = Wk + (size_t)i * DD * 512;
        const float* Wvi = Wv + (size_t)i * DD * 512;
        const float* Woi = Wo + (size_t)i * 512 * DD;
        const float* w1i = fw1 + (size_t)i * DD * 512;
        const float* w2i = fw2 + (size_t)i * 512 * DD;

        gemm_kernel<0><<<g512, 256>>>(xf, Wqi, bq + i * 512, q, BSR, 512, 128);
        gemm_kernel<0><<<g512, 256>>>(xs, Wki, bk + i * 512, k, BSR, 512, 128);
        gemm_kernel<0><<<g512, 256>>>(xs, Wvi, bv + i * 512, v, BSR, 512, 128);
        attn_kernel<<<dim3(13, HH, BB), 256, ATTN_SMEM>>>(enc);
        gemm_kernel<0><<<g128, 256>>>(s512, Woi, bo + i * DD, s128, BSR, 128, 512);
        ln_kernel<<<BSR, 128>>>(xs, s128, ln1_g + i * DD, ln1_b + i * DD);
        gemm_kernel<1><<<g512, 256>>>(xs, w1i, fb1 + i * 512, s512, BSR, 512, 128);
        gemm_kernel<0><<<g128, 256>>>(s512, w2i, fb2 + i * DD, s128, BSR, 128, 512);
        ln_kernel<<<BSR, 128>>>(xs, s128, ln2_g + i * DD, ln2_b + i * DD);
    }
    head_kernel<<<BB, 512>>>(pw1, pw2, out);
}

// round 2
// speedup vs baseline: 1.7947x; 1.7947x over previous
#include <cuda_runtime.h>
#include <math.h>

#define BB 8
#define SS 785
#define DD 128
#define HH 8
#define DHD 64
#define DFF 512
#define LL 6
#define HWP 784
#define CINC 512
#define BSR (BB*SS)   // 6280

// ------------------------- scratch (device globals) -------------------------
__device__ float g_xs[BSR*DD];
__device__ float g_xf[BSR*DD];
__device__ float g_q[BSR*512];
__device__ float g_k[BSR*512];
__device__ float g_v[BSR*512];
__device__ float g_s512[BSR*512];
__device__ float g_s128[BSR*DD];
__device__ float g_wt[CINC*DD];
__device__ float g_tb[DD];
__device__ unsigned g_maxbits;

// --------------------------- mma.sync helpers -------------------------------
__device__ __forceinline__ unsigned tf32c(float x) {
    unsigned u;
    asm("cvt.rna.tf32.f32 %0, %1;" : "=r"(u) : "f"(x));
    return u;
}
__device__ __forceinline__ void mma8(float* c, const unsigned* a, const unsigned* b) {
    asm volatile(
        "mma.sync.aligned.m16n8k8.row.col.f32.tf32.tf32.f32 "
        "{%0,%1,%2,%3}, {%4,%5,%6,%7}, {%8,%9}, {%0,%1,%2,%3};"
        : "+f"(c[0]), "+f"(c[1]), "+f"(c[2]), "+f"(c[3])
        : "r"(a[0]), "r"(a[1]), "r"(a[2]), "r"(a[3]), "r"(b[0]), "r"(b[1]));
}

// ------------------------- prep: fold BN into conv W ------------------------
__global__ void prep_kernel(const float* __restrict__ conv_w,
                            const float* __restrict__ gamma,
                            const float* __restrict__ beta,
                            const float* __restrict__ mean,
                            const float* __restrict__ var) {
    int i = blockIdx.x * blockDim.x + threadIdx.x;
    if (i == 0) g_maxbits = 0u;
    if (i < DD) {
        float s = gamma[i] * rsqrtf(var[i] + 1e-5f);
        g_tb[i] = beta[i] - mean[i] * s;
    }
    if (i < CINC * DD) {
        int c = i / DD, d = i % DD;
        float s = gamma[d] * rsqrtf(var[d] + 1e-5f);
        g_wt[i] = conv_w[d * CINC + c] * s;
    }
}

// ------------------ conv stem: 1x1 conv + BN + relu + max -------------------
__global__ __launch_bounds__(256) void conv_kernel(const float* __restrict__ x,
                                                   const float* __restrict__ y) {
    const int pb = blockIdx.x * 64;
    const int b  = blockIdx.y;
    const int st = blockIdx.z;
    const float* src = (st == 0) ? x : y;
    float* dst = (st == 0) ? g_xs : g_xf;

    __shared__ float Xs[16 * 64];   // [c][p]
    __shared__ float Ws[16 * 128];  // [c][d]

    const int t  = threadIdx.x;
    const int tx = t & 15;
    const int ty = t >> 4;

    float acc[4][8];
    #pragma unroll
    for (int i = 0; i < 4; i++)
        #pragma unroll
        for (int j = 0; j < 8; j++) acc[i][j] = 0.f;

    for (int c0 = 0; c0 < CINC; c0 += 16) {
        {
            int cc = t >> 4, pp = (t & 15) << 2;
            int p = pb + pp;
            float4 v = make_float4(0.f, 0.f, 0.f, 0.f);
            if (p < HWP)
                v = *(const float4*)&src[((size_t)(b * CINC) + (c0 + cc)) * HWP + p];
            *(float4*)&Xs[cc * 64 + pp] = v;
        }
        {
            int cc = t >> 4, ddv = (t & 15) << 3;
            const float* wp = &g_wt[(c0 + cc) * DD + ddv];
            *(float4*)&Ws[cc * 128 + ddv]     = *(const float4*)(wp);
            *(float4*)&Ws[cc * 128 + ddv + 4] = *(const float4*)(wp + 4);
        }
        __syncthreads();
        #pragma unroll
        for (int kk = 0; kk < 16; kk++) {
            float4 a  = *(float4*)&Xs[kk * 64 + (ty << 2)];
            float4 w0 = *(float4*)&Ws[kk * 128 + (tx << 3)];
            float4 w1 = *(float4*)&Ws[kk * 128 + (tx << 3) + 4];
            float av[4] = {a.x, a.y, a.z, a.w};
            float wv[8] = {w0.x, w0.y, w0.z, w0.w, w1.x, w1.y, w1.z, w1.w};
            #pragma unroll
            for (int i = 0; i < 4; i++)
                #pragma unroll
                for (int j = 0; j < 8; j++) acc[i][j] = fmaf(av[i], wv[j], acc[i][j]);
        }
        __syncthreads();
    }

    float lmax = 0.f;
    #pragma unroll
    for (int i = 0; i < 4; i++) {
        int p = pb + (ty << 2) + i;
        if (p < HWP) {
            #pragma unroll
            for (int j = 0; j < 8; j++) {
                int d = (tx << 3) + j;
                float v = fmaxf(acc[i][j] + g_tb[d], 0.f);
                lmax = fmaxf(lmax, v);
                dst[((size_t)(b * SS) + 1 + p) * DD + d] = v;
            }
        }
    }
    __shared__ float red[256];
    red[t] = lmax;
    __syncthreads();
    for (int stx = 128; stx > 0; stx >>= 1) {
        if (t < stx) red[t] = fmaxf(red[t], red[t + stx]);
        __syncthreads();
    }
    if (t == 0) atomicMax(&g_maxbits, __float_as_uint(red[0]));
}

// --------------- assemble: cls row, /max, +pos for both streams -------------
__global__ void assemble_kernel(const float* __restrict__ pos,
                                const float* __restrict__ cls) {
    int i = blockIdx.x * blockDim.x + threadIdx.x;
    if (i >= BSR * DD) return;
    float inv = 1.f / __uint_as_float(g_maxbits);
    int d = i & (DD - 1);
    int s = (i / DD) % SS;
    float p = pos[s * DD + d];
    if (s == 0) {
        float v = cls[d] + p;
        g_xs[i] = v;
        g_xf[i] = v;
    } else {
        g_xs[i] = g_xs[i] * inv + p;
        g_xf[i] = g_xf[i] * inv + p;
    }
}

// --------------------- tf32 tensor-core GEMM, bias + act --------------------
// C[M,N] = act(A[M,K] @ B[K,N] + bias[N]); K % 32 == 0, N % 128 == 0
// block: 128 threads (4 warps), tile 64(M) x 128(N), warp tile 32x64
#define SA 36
#define SB 136
template <int ACT>
__global__ __launch_bounds__(128) void gemm_kernel(const float* __restrict__ A,
                                                   const float* __restrict__ Bm,
                                                   const float* __restrict__ bias,
                                                   float* __restrict__ C,
                                                   int M, int N, int K) {
    __shared__ unsigned As[64 * SA];
    __shared__ unsigned Bs[32 * SB];
    const int t = threadIdx.x;
    const int lane = t & 31, w = t >> 5;
    const int group = lane >> 2, tig = lane & 3;
    const int wm = w & 1, wn = w >> 1;
    const int m0 = blockIdx.y * 64, n0 = blockIdx.x * 128;

    float acc[2][8][4];
    #pragma unroll
    for (int mi = 0; mi < 2; mi++)
        #pragma unroll
        for (int ni = 0; ni < 8; ni++)
            #pragma unroll
            for (int r = 0; r < 4; r++) acc[mi][ni][r] = 0.f;

    for (int k0 = 0; k0 < K; k0 += 32) {
        // stage A tile 64x32 (tf32)
        #pragma unroll
        for (int p = 0; p < 4; p++) {
            int row = p * 16 + (t >> 3);
            int c4 = (t & 7) << 2;
            float4 v = make_float4(0.f, 0.f, 0.f, 0.f);
            if (m0 + row < M)
                v = *(const float4*)&A[(size_t)(m0 + row) * K + k0 + c4];
            As[row * SA + c4 + 0] = tf32c(v.x);
            As[row * SA + c4 + 1] = tf32c(v.y);
            As[row * SA + c4 + 2] = tf32c(v.z);
            As[row * SA + c4 + 3] = tf32c(v.w);
        }
        // stage B tile 32x128 (tf32)
        #pragma unroll
        for (int p = 0; p < 2; p++) {
            int row = p * 16 + (t >> 3);
            int cb = (t & 7) << 2;
            #pragma unroll
            for (int i = 0; i < 4; i++) {
                float4 v = *(const float4*)&Bm[(size_t)(k0 + row) * N + n0 + cb + i * 32];
                Bs[row * SB + cb + i * 32 + 0] = tf32c(v.x);
                Bs[row * SB + cb + i * 32 + 1] = tf32c(v.y);
                Bs[row * SB + cb + i * 32 + 2] = tf32c(v.z);
                Bs[row * SB + cb + i * 32 + 3] = tf32c(v.w);
            }
        }
        __syncthreads();
        #pragma unroll
        for (int kk = 0; kk < 32; kk += 8) {
            unsigned af[2][4];
            #pragma unroll
            for (int mi = 0; mi < 2; mi++) {
                int base = wm * 32 + mi * 16 + group;
                af[mi][0] = As[base * SA + kk + tig];
                af[mi][1] = As[(base + 8) * SA + kk + tig];
                af[mi][2] = As[base * SA + kk + tig + 4];
                af[mi][3] = As[(base + 8) * SA + kk + tig + 4];
            }
            unsigned bf[8][2];
            #pragma unroll
            for (int ni = 0; ni < 8; ni++) {
                int col = wn * 64 + ni * 8 + group;
                bf[ni][0] = Bs[(kk + tig) * SB + col];
                bf[ni][1] = Bs[(kk + tig + 4) * SB + col];
            }
            #pragma unroll
            for (int mi = 0; mi < 2; mi++)
                #pragma unroll
                for (int ni = 0; ni < 8; ni++)
                    mma8(acc[mi][ni], af[mi], bf[ni]);
        }
        __syncthreads();
    }

    // epilogue
    #pragma unroll
    for (int mi = 0; mi < 2; mi++) {
        int row0 = m0 + wm * 32 + mi * 16 + group;
        #pragma unroll
        for (int ni = 0; ni < 8; ni++) {
            int col = n0 + wn * 64 + ni * 8 + tig * 2;
            float b0 = bias[col], b1 = bias[col + 1];
            if (row0 < M) {
                float v0 = acc[mi][ni][0] + b0;
                float v1 = acc[mi][ni][1] + b1;
                if (ACT == 1) { v0 = v0 * normcdff(v0); v1 = v1 * normcdff(v1); }
                *(float2*)&C[(size_t)row0 * N + col] = make_float2(v0, v1);
            }
            if (row0 + 8 < M) {
                float v2 = acc[mi][ni][2] + b0;
                float v3 = acc[mi][ni][3] + b1;
                if (ACT == 1) { v2 = v2 * normcdff(v2); v3 = v3 * normcdff(v3); }
                *(float2*)&C[(size_t)(row0 + 8) * N + col] = make_float2(v2, v3);
            }
        }
    }
}

// --------------- fused flash attention, tf32 tensor cores -------------------
// grid (13, H, B), 128 threads (4 warps, 16 queries each)
#define SK 72
#define SP 68
__global__ __launch_bounds__(128) void attn_kernel(const int* __restrict__ enc) {
    extern __shared__ unsigned dsm[];
    unsigned* Ks = dsm;                 // [d][key]  64 x 72
    unsigned* Vs = dsm + 64 * SK;       // [key][d]  64 x 72
    unsigned* Ps = dsm + 2 * 64 * SK;   // [i][key]  64 x 68
    float* maskv = (float*)(dsm + 2 * 64 * SK + 64 * SP);  // [64]

    const int qt = blockIdx.x, h = blockIdx.y, b = blockIdx.z;
    const int t = threadIdx.x;
    const int lane = t & 31, w = t >> 5;
    const int group = lane >> 2, tig = lane & 3;

    // load Q fragments into registers (tf32), rows qbase+group, +8
    unsigned qa[8][4];
    {
        int r0 = qt * 64 + w * 16 + group;
        int s0 = (r0 < SS) ? r0 : SS - 1;
        int s1 = (r0 + 8 < SS) ? r0 + 8 : SS - 1;
        const float* q0p = &g_q[(size_t)(b * SS + s0) * 512 + h * 64];
        const float* q1p = &g_q[(size_t)(b * SS + s1) * 512 + h * 64];
        #pragma unroll
        for (int ks = 0; ks < 8; ks++) {
            int col = ks * 8 + tig;
            qa[ks][0] = tf32c(q0p[col]);
            qa[ks][1] = tf32c(q1p[col]);
            qa[ks][2] = tf32c(q0p[col + 4]);
            qa[ks][3] = tf32c(q1p[col + 4]);
        }
    }

    float mv0 = -1e30f, mv1 = -1e30f, l0 = 0.f, l1 = 0.f;
    float o[8][4];
    #pragma unroll
    for (int dn = 0; dn < 8; dn++)
        #pragma unroll
        for (int r = 0; r < 4; r++) o[dn][r] = 0.f;
    const float scale = 0.125f;

    for (int t0 = 0; t0 < SS; t0 += 64) {
        __syncthreads();
        // stage K (transposed, tf32), V (row, tf32), mask
        {
            int j = t >> 1, dh = (t & 1) * 32;
            int s = t0 + j;
            bool ok = s < SS;
            int ss = ok ? s : SS - 1;
            const float* kp = &g_k[(size_t)(b * SS + ss) * 512 + h * 64 + dh];
            const float* vp = &g_v[(size_t)(b * SS + ss) * 512 + h * 64 + dh];
            #pragma unroll
            for (int i = 0; i < 8; i++) {
                float4 kv = ok ? *(const float4*)(kp + i * 4) : make_float4(0, 0, 0, 0);
                Ks[(dh + i * 4 + 0) * SK + j] = tf32c(kv.x);
                Ks[(dh + i * 4 + 1) * SK + j] = tf32c(kv.y);
                Ks[(dh + i * 4 + 2) * SK + j] = tf32c(kv.z);
                Ks[(dh + i * 4 + 3) * SK + j] = tf32c(kv.w);
                float4 vv = ok ? *(const float4*)(vp + i * 4) : make_float4(0, 0, 0, 0);
                uint4 pk;
                pk.x = tf32c(vv.x); pk.y = tf32c(vv.y);
                pk.z = tf32c(vv.z); pk.w = tf32c(vv.w);
                *(uint4*)&Vs[j * SK + dh + i * 4] = pk;
            }
            if ((t & 1) == 0)
                maskv[j] = (ok && enc[b * SS + s] != 0) ? 0.f : -1e9f;
        }
        __syncthreads();

        // S = Q K^T
        float sc[8][4];
        #pragma unroll
        for (int nj = 0; nj < 8; nj++)
            #pragma unroll
            for (int r = 0; r < 4; r++) sc[nj][r] = 0.f;
        #pragma unroll
        for (int ks = 0; ks < 8; ks++) {
            #pragma unroll
            for (int nj = 0; nj < 8; nj++) {
                unsigned bf[2];
                bf[0] = Ks[(ks * 8 + tig) * SK + nj * 8 + group];
                bf[1] = Ks[(ks * 8 + tig + 4) * SK + nj * 8 + group];
                mma8(sc[nj], qa[ks], bf);
            }
        }

        // scale + mask + online softmax
        float mx0 = -1e30f, mx1 = -1e30f;
        #pragma unroll
        for (int nj = 0; nj < 8; nj++) {
            float mk0 = maskv[nj * 8 + tig * 2];
            float mk1 = maskv[nj * 8 + tig * 2 + 1];
            sc[nj][0] = sc[nj][0] * scale + mk0;
            sc[nj][1] = sc[nj][1] * scale + mk1;
            sc[nj][2] = sc[nj][2] * scale + mk0;
            sc[nj][3] = sc[nj][3] * scale + mk1;
            mx0 = fmaxf(mx0, fmaxf(sc[nj][0], sc[nj][1]));
            mx1 = fmaxf(mx1, fmaxf(sc[nj][2], sc[nj][3]));
        }
        mx0 = fmaxf(mx0, __shfl_xor_sync(~0u, mx0, 1));
        mx0 = fmaxf(mx0, __shfl_xor_sync(~0u, mx0, 2));
        mx1 = fmaxf(mx1, __shfl_xor_sync(~0u, mx1, 1));
        mx1 = fmaxf(mx1, __shfl_xor_sync(~0u, mx1, 2));
        float nm0 = fmaxf(mv0, mx0), nm1 = fmaxf(mv1, mx1);
        float f0 = __expf(mv0 - nm0), f1 = __expf(mv1 - nm1);
        float rs0 = 0.f, rs1 = 0.f;
        int prow = w * 16 + group;
        #pragma unroll
        for (int nj = 0; nj < 8; nj++) {
            float p0 = __expf(sc[nj][0] - nm0);
            float p1 = __expf(sc[nj][1] - nm0);
            float p2 = __expf(sc[nj][2] - nm1);
            float p3 = __expf(sc[nj][3] - nm1);
            rs0 += p0 + p1;
            rs1 += p2 + p3;
            uint2 u0; u0.x = tf32c(p0); u0.y = tf32c(p1);
            uint2 u1; u1.x = tf32c(p2); u1.y = tf32c(p3);
            *(uint2*)&Ps[prow * SP + nj * 8 + tig * 2] = u0;
            *(uint2*)&Ps[(prow + 8) * SP + nj * 8 + tig * 2] = u1;
        }
        rs0 += __shfl_xor_sync(~0u, rs0, 1);
        rs0 += __shfl_xor_sync(~0u, rs0, 2);
        rs1 += __shfl_xor_sync(~0u, rs1, 1);
        rs1 += __shfl_xor_sync(~0u, rs1, 2);
        l0 = l0 * f0 + rs0;
        l1 = l1 * f1 + rs1;
        mv0 = nm0; mv1 = nm1;
        #pragma unroll
        for (int dn = 0; dn < 8; dn++) {
            o[dn][0] *= f0; o[dn][1] *= f0;
            o[dn][2] *= f1; o[dn][3] *= f1;
        }
        __syncwarp();

        // O += P V
        #pragma unroll
        for (int ks = 0; ks < 8; ks++) {
            unsigned pa[4];
            pa[0] = Ps[prow * SP + ks * 8 + tig];
            pa[1] = Ps[(prow + 8) * SP + ks * 8 + tig];
            pa[2] = Ps[prow * SP + ks * 8 + tig + 4];
            pa[3] = Ps[(prow + 8) * SP + ks * 8 + tig + 4];
            #pragma unroll
            for (int dn = 0; dn < 8; dn++) {
                unsigned bf[2];
                bf[0] = Vs[(ks * 8 + tig) * SK + dn * 8 + group];
                bf[1] = Vs[(ks * 8 + tig + 4) * SK + dn * 8 + group];
                mma8(o[dn], pa, bf);
            }
        }
    }

    // epilogue
    float il0 = 1.f / l0, il1 = 1.f / l1;
    int sq0 = qt * 64 + w * 16 + group;
    #pragma unroll
    for (int dn = 0; dn < 8; dn++) {
        int col = h * 64 + dn * 8 + tig * 2;
        if (sq0 < SS)
            *(float2*)&g_s512[(size_t)(b * SS + sq0) * 512 + col] =
                make_float2(o[dn][0] * il0, o[dn][1] * il0);
        if (sq0 + 8 < SS)
            *(float2*)&g_s512[(size_t)(b * SS + sq0 + 8) * 512 + col] =
                make_float2(o[dn][2] * il1, o[dn][3] * il1);
    }
}

// ---------------- residual add + LayerNorm (in-place on g_xs) ---------------
__global__ void ln_kernel(float* __restrict__ xs, const float* __restrict__ add,
                          const float* __restrict__ g, const float* __restrict__ bb) {
    int r = blockIdx.x;
    int d = threadIdx.x;
    float v = xs[(size_t)r * DD + d] + add[(size_t)r * DD + d];
    __shared__ float sred[4];
    float sv = v;
    #pragma unroll
    for (int off = 16; off > 0; off >>= 1) sv += __shfl_xor_sync(~0u, sv, off);
    if ((d & 31) == 0) sred[d >> 5] = sv;
    __syncthreads();
    float mu = (sred[0] + sred[1] + sred[2] + sred[3]) * (1.f / 128.f);
    float c = v - mu;
    float sq = c * c;
    #pragma unroll
    for (int off = 16; off > 0; off >>= 1) sq += __shfl_xor_sync(~0u, sq, off);
    __syncthreads();
    if ((d & 31) == 0) sred[d >> 5] = sq;
    __syncthreads();
    float var = (sred[0] + sred[1] + sred[2] + sred[3]) * (1.f / 128.f);
    xs[(size_t)r * DD + d] = c * rsqrtf(var + 1e-12f) * g[d] + bb[d];
}

// --------------------------------- head -------------------------------------
__global__ void head_kernel(const float* __restrict__ w1,
                            const float* __restrict__ w2,
                            float* __restrict__ out) {
    int b = blockIdx.x, j = threadIdx.x;
    const float* xr = &g_xs[(size_t)(b * SS) * DD];
    float s = 0.f;
    #pragma unroll
    for (int d = 0; d < DD; d++) s = fmaf(xr[d], w1[d * 512 + j], s);
    s = fmaxf(s, 0.f) * w2[j];
    __shared__ float red[512];
    red[j] = s;
    __syncthreads();
    for (int st = 256; st > 0; st >>= 1) {
        if (j < st) red[j] += red[j + st];
        __syncthreads();
    }
    if (j == 0) out[b] = red[0];
}

// ------------------------------ launcher ------------------------------------
extern "C" void kernel_launch(void* const* d_in, const int* in_sizes, int n_in,
                              void* d_out, int out_size) {
    const float* conv_w   = (const float*)d_in[0];
    const float* bn_gamma = (const float*)d_in[1];
    const float* bn_beta  = (const float*)d_in[2];
    const float* bn_mean  = (const float*)d_in[3];
    const float* bn_var   = (const float*)d_in[4];
    const float* pos_emb  = (const float*)d_in[5];
    const float* cls_tok  = (const float*)d_in[6];
    const float* Wq = (const float*)d_in[7];
    const float* bq = (const float*)d_in[8];
    const float* Wk = (const float*)d_in[9];
    const float* bk = (const float*)d_in[10];
    const float* Wv = (const float*)d_in[11];
    const float* bv = (const float*)d_in[12];
    const float* Wo = (const float*)d_in[13];
    const float* bo = (const float*)d_in[14];
    const float* ln1_g = (const float*)d_in[15];
    const float* ln1_b = (const float*)d_in[16];
    const float* fw1 = (const float*)d_in[17];
    const float* fb1 = (const float*)d_in[18];
    const float* fw2 = (const float*)d_in[19];
    const float* fb2 = (const float*)d_in[20];
    const float* ln2_g = (const float*)d_in[21];
    const float* ln2_b = (const float*)d_in[22];
    const float* pw1 = (const float*)d_in[23];
    const float* pw2 = (const float*)d_in[24];
    const int*   enc = (const int*)d_in[25];
    const float* x   = (const float*)d_in[26];
    const float* y   = (const float*)d_in[27];
    float* out = (float*)d_out;

    float *xs, *xf, *q, *k, *v, *s512, *s128;
    cudaGetSymbolAddress((void**)&xs,   g_xs);
    cudaGetSymbolAddress((void**)&xf,   g_xf);
    cudaGetSymbolAddress((void**)&q,    g_q);
    cudaGetSymbolAddress((void**)&k,    g_k);
    cudaGetSymbolAddress((void**)&v,    g_v);
    cudaGetSymbolAddress((void**)&s512, g_s512);
    cudaGetSymbolAddress((void**)&s128, g_s128);

    const int ATTN_SMEM = (2 * 64 * SK + 64 * SP + 64) * (int)sizeof(unsigned);
    cudaFuncSetAttribute(attn_kernel, cudaFuncAttributeMaxDynamicSharedMemorySize,
                         ATTN_SMEM);

    prep_kernel<<<(CINC * DD + 255) / 256, 256>>>(conv_w, bn_gamma, bn_beta,
                                                  bn_mean, bn_var);
    conv_kernel<<<dim3(13, BB, 2), 256>>>(x, y);
    assemble_kernel<<<(BSR * DD + 255) / 256, 256>>>(pos_emb, cls_tok);

    const int MB = (BSR + 63) / 64;  // 99
    const dim3 g512(4, MB);
    const dim3 g128(1, MB);

    for (int i = 0; i < LL; i++) {
        const float* Wqi = Wq + (size_t)i * DD * 512;
        const float* Wki = Wk + (size_t)i * DD * 512;
        const float* Wvi = Wv + (size_t)i * DD * 512;
        const float* Woi = Wo + (size_t)i * 512 * DD;
        const float* w1i = fw1 + (size_t)i * DD * 512;
        const float* w2i = fw2 + (size_t)i * 512 * DD;

        gemm_kernel<0><<<g512, 128>>>(xf, Wqi, bq + i * 512, q, BSR, 512, 128);
        gemm_kernel<0><<<g512, 128>>>(xs, Wki, bk + i * 512, k, BSR, 512, 128);
        gemm_kernel<0><<<g512, 128>>>(xs, Wvi, bv + i * 512, v, BSR, 512, 128);
        attn_kernel<<<dim3(13, HH, BB), 128, ATTN_SMEM>>>(enc);
        gemm_kernel<0><<<g128, 128>>>(s512, Woi, bo + i * DD, s128, BSR, 128, 512);
        ln_kernel<<<BSR, 128>>>(xs, s128, ln1_g + i * DD, ln1_b + i * DD);
        gemm_kernel<1><<<g512, 128>>>(xs, w1i, fb1 + i * 512, s512, BSR, 512, 128);
        gemm_kernel<0><<<g128, 128>>>(s512, w2i, fb2 + i * DD, s128, BSR, 128, 512);
        ln_kernel<<<BSR, 128>>>(xs, s128, ln2_g + i * DD, ln2_b + i * DD);
    }
    head_kernel<<<BB, 512>>>(pw1, pw2, out);
}